// round 17
// baseline (speedup 1.0000x reference)
#include <cuda_runtime.h>
#include <cuda_bf16.h>
#include <cstdint>

// ---------------------------------------------------------------------------
// 2-layer LSTM, B=64, S=512, I=64, H=512, fc head on final h1.
// R17 = R16 (128 CTAs x 256 thr, one layer per CTA, 8 h-cols, split-K teams,
// single-poller waits, owner inversion, one __syncthreads per phase) with:
//  * deeper cp.async pipeline: 6 slots, 5 chunks in flight (wait_group 4)
//    -> fill lead covers burst-inflated L2 latency.
//  * chunk issue moved AFTER the per-iteration barrier -> the warp-skew
//    slot-overwrite race (previously masked by cp.async flight time) is
//    structurally gone; phase-boundary reuse ordered by the phase sync/bars.
//  * layer0 h0-ring back-pressure wait moved to team0 (overlapped), out of
//    the owner team's critical tail.
// Counters: g_c0 = 128 + 64*(q+1) after all layer0 finish phase q;
//           g_c1 = 64*(q+1) after all layer1 finish phase q (q=0 equalizer).
// h0 ring 8 deep, h1 ring 4 deep, creg/bias owned by team1 (owner).
// bf16 mma.m16n8k16 fp32-acc. Exit protocol resets counters (replay-safe).
// ---------------------------------------------------------------------------

#define NC    128
#define NTHR  256
#define BSZ   64
#define SEQ   512

#define AROWW 64
#define ASTR  72
#define CHKP  32
#define SLOTW (CHKP*ASTR)             // 2304 words per slot
#define NSLOT 6                       // 5 chunks in flight
#define WSTR  40

#define KP0   288
#define KP1   512

#define SW_OFF    0
#define SBIAS_OFF 20480                       // 512*40 max weight words
#define SRED_OFF  (SBIAS_OFF + 32)            // 2 x 2048-word acc buffers
#define SA_OFF    (SRED_OFF + 4096)           // 24608
#define SMEM_WORDS (SA_OFF + 2*NSLOT*SLOTW)   // 52256
#define SMEM_BYTES (SMEM_WORDS*4)             // 209024

__device__ uint32_t g_xw[SEQ*32*BSZ];
__device__ uint32_t g_h0w[8][256*BSZ];
__device__ uint32_t g_h1w[4][256*BSZ];
__device__ unsigned g_c0;
__device__ unsigned g_c1;
__device__ unsigned g_done;

__device__ __forceinline__ uint32_t packbf2(float lo, float hi) {
    uint32_t r;
    asm("cvt.rn.bf16x2.f32 %0, %1, %2;" : "=r"(r) : "f"(hi), "f"(lo));
    return r;
}

__device__ __forceinline__ void mma16(float (&d)[4],
                                      uint32_t a0, uint32_t a1, uint32_t a2, uint32_t a3,
                                      uint32_t b0, uint32_t b1) {
    asm volatile(
        "mma.sync.aligned.m16n8k16.row.col.f32.bf16.bf16.f32 "
        "{%0,%1,%2,%3}, {%4,%5,%6,%7}, {%8,%9}, {%0,%1,%2,%3};"
        : "+f"(d[0]), "+f"(d[1]), "+f"(d[2]), "+f"(d[3])
        : "r"(a0), "r"(a1), "r"(a2), "r"(a3), "r"(b0), "r"(b1));
}

__device__ __forceinline__ float fast_tanh(float x) {
    float r;
    asm("tanh.approx.f32 %0, %1;" : "=f"(r) : "f"(x));
    return r;
}
__device__ __forceinline__ float sigm(float x) {
    return 0.5f * fast_tanh(0.5f * x) + 0.5f;
}

__device__ __forceinline__ void cpa16(uint32_t d, const uint32_t* s) {
    asm volatile("cp.async.cg.shared.global [%0], [%1], 16;" :: "r"(d), "l"(s) : "memory");
}
#define CP_COMMIT() asm volatile("cp.async.commit_group;" ::: "memory")
#define CP_WAIT4()  asm volatile("cp.async.wait_group 4;" ::: "memory")
#define BAR_WG(id)  asm volatile("bar.sync %0, 128;" :: "r"(id) : "memory")

__device__ __forceinline__ unsigned ldacq(const unsigned* p) {
    unsigned v;
    asm volatile("ld.acquire.gpu.global.u32 %0, [%1];" : "=r"(v) : "l"(p));
    return v;
}
__device__ __forceinline__ void redrel(unsigned* p) {
    asm volatile("red.release.gpu.global.add.u32 [%0], %1;" :: "l"(p), "r"(1u) : "memory");
}
__device__ __forceinline__ void wait_ge(unsigned* ctr, unsigned tgt) {
    while ((int)(ldacq(ctr) - tgt) < 0) { }
}
// single-poller team wait: warp0 of the team polls, named bar releases team
__device__ __forceinline__ void team_wait(unsigned* ctr, unsigned tgt,
                                          int wrp4, int barid) {
    if (wrp4 == 0) wait_ge(ctr, tgt);
    BAR_WG(barid);
}

__device__ __forceinline__ void issue_chunk(const uint32_t* __restrict__ src,
                                            uint32_t dstAdr) {
    cpa16(dstAdr,      src);
    cpa16(dstAdr + 16, src + 4);
    cpa16(dstAdr + 32, src + 8);
    cpa16(dstAdr + 48, src + 12);
}

__device__ __forceinline__ const uint32_t* chunk_src(int cn, int lyr,
        const uint32_t* pX, const uint32_t* pHa, const uint32_t* pHb) {
    if (!lyr) return (cn == 0) ? pX : pHa + (cn - 1) * (CHKP * AROWW);
    return (cn < 8) ? pHa + cn * (CHKP * AROWW)
                    : pHb + (cn - 8) * (CHKP * AROWW);
}

__global__ void __launch_bounds__(NTHR, 1)
lstm_persist(const float* __restrict__ W0, const float* __restrict__ b0,
             const float* __restrict__ W1, const float* __restrict__ b1,
             const float* __restrict__ Wfc, const float* __restrict__ bfc,
             float* __restrict__ out) {
    extern __shared__ uint32_t sm[];
    float* sBias = (float*)(sm + SBIAS_OFF);

    const int cta  = blockIdx.x;
    const int tid  = threadIdx.x;
    const int lyr  = cta >> 6;
    const int lc   = cta & 63;
    const int n0   = lc * 8;
    const int lane = tid & 31, wrp = tid >> 5;
    const int wrp4 = wrp & 3;
    const int team = wrp >> 2;
    const int g    = lane >> 2, t4 = lane & 3;
    const int rowa = wrp4 * 16 + g;

    const int tid7 = tid & 127;
    const int ldr  = tid7 >> 2;
    const int ldc  = (tid7 & 3) * 16;
    const int thrOff = ldr * AROWW + ldc;

    const int barid = 1 + team;
    const uint32_t smBase = (uint32_t)__cvta_generic_to_shared(sm);
    const uint32_t saTeam = smBase + (SA_OFF + team * NSLOT * SLOTW) * 4
                          + (ldr * ASTR + ldc) * 4;
    const uint32_t* sAteam = sm + SA_OFF + team * NSLOT * SLOTW;
    const int kpIdx = lc * 4 + t4;

    const int base = lyr ? (team ? 8 : 0) : (team ? 5 : 0);
    const int nCh  = lyr ? 8 : (team ? 4 : 5);

    // ---- prologue ----
    for (int e = cta * NTHR + tid; e < 256 * BSZ; e += NC * NTHR) {
        g_h0w[7][e] = 0u;
        g_h1w[3][e] = 0u;
    }
    {
        const float* W    = lyr ? W1 : W0;
        const float* bias = lyr ? b1 : b0;
        const int KW = lyr ? KP1 : KP0;
        for (int e = tid; e < KW * 32; e += NTHR) {
            int kp = e >> 5, c = e & 31;
            int q = c >> 3, j = c & 7;
            const float* w = W + (2 * kp) * 2048 + q * 512 + n0 + j;
            sm[SW_OFF + kp * WSTR + c] = packbf2(w[0], w[2048]);
        }
        if (tid < 32) {
            int q = tid >> 3, j = tid & 7;
            sBias[tid] = bias[q * 512 + n0 + j];
        }
    }

    __syncthreads();
    if (tid == 0) {
        redrel(&g_c0);                          // init: g_c0 -> 128
        if (lyr) redrel(&g_c1);                 // equalizer: g_c1 -> 64
    }

    float creg[4] = {0.f, 0.f, 0.f, 0.f};       // live in team1 only
    float accb[4][2];
#pragma unroll
    for (int q = 0; q < 4; ++q) {                // bias owned by team1
        accb[q][0] = team ? sBias[q * 8 + 2 * t4]     : 0.f;
        accb[q][1] = team ? sBias[q * 8 + 2 * t4 + 1] : 0.f;
    }

    const int pStart = lyr ? 1 : 0;
    const int pEnd   = lyr ? SEQ : (SEQ - 1);

    for (int p = pStart; p <= pEnd; ++p) {
        const uint32_t* pX  = g_xw + p * (32 * BSZ) + thrOff;
        const uint32_t* pHa = g_h0w[(p + 7) & 7] + thrOff;      // h0(p-1)
        const uint32_t* pHb = g_h1w[(p + 2) & 3] + thrOff;      // h1(p-2)

        // ---- dependency wait + ring prologue: 5 chunks in flight ----
        if (!lyr && !team) {
            issue_chunk(pX, saTeam);                    // x: no dependency
            CP_COMMIT();
            team_wait(&g_c0, 128u + 64u * p, wrp4, barid);
#pragma unroll
            for (int k = 1; k < 5; ++k) {               // nCh = 5 here
                issue_chunk(chunk_src(k, 0, pX, pHa, pHb),
                            saTeam + k * (SLOTW * 4));
                CP_COMMIT();
            }
        } else {
            if (lyr && team) team_wait(&g_c1, 64u * p, wrp4, barid);
            else             team_wait(&g_c0, 128u + 64u * p, wrp4, barid);
#pragma unroll
            for (int k = 0; k < 5; ++k) {
                if (k < nCh)
                    issue_chunk(chunk_src(base + k, lyr, pX, pHa, pHb),
                                saTeam + k * (SLOTW * 4));
                CP_COMMIT();
            }
        }

        float acc[4][4];
#pragma unroll
        for (int q = 0; q < 4; ++q) {
            acc[q][0] = accb[q][0]; acc[q][1] = accb[q][1];
            acc[q][2] = accb[q][0]; acc[q][3] = accb[q][1];
        }

        // ---- chunk pipeline: wait -> bar -> issue(c+5) -> compute(c) ----
        for (int c = 0; c < nCh; ++c) {
            CP_WAIT4();                          // chunk c resident
            BAR_WG(barid);                       // all warps past chunk c-1
            int cl = c + 5;
            if (cl < nCh)                        // safe: after the bar
                issue_chunk(chunk_src(base + cl, lyr, pX, pHa, pHb),
                            saTeam + (cl % NSLOT) * (SLOTW * 4));
            CP_COMMIT();
            const uint32_t* As = sAteam + (c % NSLOT) * SLOTW;
            const int cn = base + c;
#pragma unroll
            for (int k16 = 0; k16 < 4; ++k16) {
                const uint32_t* ap = As + (k16 * 8 + t4) * ASTR;
                uint32_t a0 = ap[rowa];
                uint32_t a1 = ap[rowa + 8];
                uint32_t a2 = ap[4 * ASTR + rowa];
                uint32_t a3 = ap[4 * ASTR + rowa + 8];
                const uint32_t* bp = sm + ((cn * 4 + k16) * 8 + t4) * WSTR + g;
#pragma unroll
                for (int q = 0; q < 4; ++q)
                    mma16(acc[q], a0, a1, a2, a3, bp[q * 8], bp[4 * WSTR + q * 8]);
            }
        }

        // ---- handoff: team0 dumps BEFORE the single sync; team1 tails ----
        float* red = (float*)(sm + SRED_OFF) + (p & 1) * 2048
                   + (wrp4 * 32 + lane) * 16;
        if (!team) {
            // layer0 h0-ring back-pressure, overlapped here (off-critical);
            // the __syncthreads below orders it before team1's store.
            if (!lyr && p >= 7) team_wait(&g_c1, 64u * (p - 6), wrp4, barid);
#pragma unroll
            for (int q = 0; q < 4; ++q)
                *(float4*)(red + q * 4) = *(float4*)acc[q];
        }
        __syncthreads();                         // the ONE join per phase
        if (team) {
#pragma unroll
            for (int q = 0; q < 4; ++q) {
                float4 r4 = *(const float4*)(red + q * 4);
                acc[q][0] += r4.x; acc[q][1] += r4.y;
                acc[q][2] += r4.z; acc[q][3] += r4.w;
            }

            uint32_t* hw = lyr ? g_h1w[(p - 1) & 3] : g_h0w[p & 7];
            float hv[4];
#pragma unroll
            for (int pr = 0; pr < 4; ++pr) {
                float cn2 = sigm(acc[1][pr]) * creg[pr]
                          + sigm(acc[0][pr]) * fast_tanh(acc[2][pr]);
                creg[pr] = cn2;
                hv[pr] = sigm(acc[3][pr]) * fast_tanh(cn2);
            }
            __stcg(&hw[kpIdx * BSZ + rowa],     packbf2(hv[0], hv[1]));
            __stcg(&hw[kpIdx * BSZ + rowa + 8], packbf2(hv[2], hv[3]));
            BAR_WG(barid);                       // order team1 stores
            if (tid7 == 0) redrel(lyr ? &g_c1 : &g_c0);
        }
    }

    // ---- epilogue: fc head on final h1 (one layer1 CTA) ----
    if (cta == NC - 1) {
        wait_ge(&g_c1, 64u * (SEQ + 1));
        if (tid < BSZ) {
            const uint32_t* h = g_h1w[(SEQ - 1) & 3];
            float s0 = 0.f, s1 = 0.f;
#pragma unroll 4
            for (int kp = 0; kp < 256; ++kp) {
                uint32_t w = __ldcg(&h[kp * BSZ + tid]);
                float lo = __bfloat162float(__ushort_as_bfloat16((unsigned short)(w & 0xFFFF)));
                float hi = __bfloat162float(__ushort_as_bfloat16((unsigned short)(w >> 16)));
                s0 += lo * Wfc[2 * kp];
                s1 += hi * Wfc[2 * kp + 1];
            }
            out[tid] = s0 + s1 + bfc[0];
        }
    }

    // ---- exit protocol: reset counters for the next graph replay ----
    __syncthreads();
    if (tid == 0) redrel(&g_done);
    if (cta == 0 && tid == 0) {
        unsigned v;
        do {
            asm volatile("ld.acquire.gpu.global.u32 %0, [%1];" : "=r"(v) : "l"(&g_done));
        } while ((int)(v - NC) < 0);
        *(volatile unsigned*)&g_c0 = 0u;
        *(volatile unsigned*)&g_c1 = 0u;
        *(volatile unsigned*)&g_done = 0u;
    }
}

// x[b][t][i] -> pair-words [t][kp][b]
__global__ void xpose_kernel(const float* __restrict__ x) {
    int idx = blockIdx.x * blockDim.x + threadIdx.x;
    if (idx < SEQ * 32 * BSZ) {
        int b  = idx & 63;
        int kp = (idx >> 6) & 31;
        int t  = idx >> 11;
        const float* xe = x + ((b * SEQ) + t) * 64 + 2 * kp;
        g_xw[idx] = packbf2(xe[0], xe[1]);
    }
}

extern "C" void kernel_launch(void* const* d_in, const int* in_sizes, int n_in,
                              void* d_out, int out_size) {
    (void)in_sizes; (void)n_in; (void)out_size;
    const float* x   = (const float*)d_in[0];
    const float* W0  = (const float*)d_in[1];
    const float* b0  = (const float*)d_in[2];
    const float* W1  = (const float*)d_in[3];
    const float* b1  = (const float*)d_in[4];
    const float* Wfc = (const float*)d_in[5];
    const float* bfc = (const float*)d_in[6];
    float* out = (float*)d_out;

    cudaFuncSetAttribute(lstm_persist,
                         cudaFuncAttributeMaxDynamicSharedMemorySize, SMEM_BYTES);

    xpose_kernel<<<(SEQ * 32 * BSZ + 255) / 256, 256>>>(x);
    lstm_persist<<<NC, NTHR, SMEM_BYTES>>>(W0, b0, W1, b1, Wfc, bfc, out);
}